// round 4
// baseline (speedup 1.0000x reference)
#include <cuda_runtime.h>
#include <math.h>
#include <stdint.h>

// Problem constants
#define CKD 64
#define QD 1620          // H*W = 30*54
#define OD 3
#define CVD 512
#define MD 32400
#define TOPK 20
#define CHD 1536         // OD*CVD

// K1 tiling: 13 q-blocks x 11 chunks = 143 blocks (single wave on 148 SMs)
#define NCHUNK 11
#define CHUNKP 3072      // chunk stride (24 tiles of 128); 11*3072 = 33792 >= 32400
#define QT 128           // q per K1 block
#define MT 128           // m tile per iteration
#define NQB 13           // ceil(QD/QT) -> 13*128 = 1664
#define CAP 16           // candidate buffer capacity per q per tile

// K3 tiling
#define QT3 16

// ---------------- device scratch (static globals, no allocation) -------------
__device__ float g_nasq[MD];                       // -0.125 * ||mk_m||^2
__device__ float g_vt[(size_t)MD * CHD];           // transposed mem_v [M][1536]
__device__ float g_pval[QD * NCHUNK * TOPK];       // per-chunk partial topk vals [q][chunk][20]
__device__ int   g_pidx[QD * NCHUNK * TOPK];       // per-chunk partial topk idx
__device__ float g_wval[QD * TOPK];                // softmax weights
__device__ int   g_widx[QD * TOPK];                // selected m indices
__device__ float g_dummy_sink[1];

// ---------------- packed f32x2 helpers ---------------------------------------
__device__ __forceinline__ unsigned long long dup2(float v) {
    unsigned long long r;
    asm("mov.b64 %0, {%1, %1};" : "=l"(r) : "f"(v));
    return r;
}
__device__ __forceinline__ void ffma2(unsigned long long& d, unsigned long long a,
                                      unsigned long long b) {
    asm("fma.rn.f32x2 %0, %1, %2, %0;" : "+l"(d) : "l"(a), "l"(b));
}
__device__ __forceinline__ unsigned long long ffma2o(unsigned long long a,
                                                     unsigned long long b,
                                                     unsigned long long c) {
    unsigned long long d;
    asm("fma.rn.f32x2 %0, %1, %2, %3;" : "=l"(d) : "l"(a), "l"(b), "l"(c));
    return d;
}

// ---------------- K0: negated scaled a_sq precompute --------------------------
__global__ void k_asq(const float* __restrict__ mk) {
    int m = blockIdx.x * 256 + threadIdx.x;
    if (m >= MD) return;
    float s = 0.f;
    #pragma unroll
    for (int c = 0; c < CKD; c++) {
        float v = mk[c * MD + m];
        s += v * v;
    }
    g_nasq[m] = -(s * 0.125f);
}

// ---------------- KT: transpose mem_v [1536][M] -> v_t [M][1536] --------------
__global__ void k_transpose(const float* __restrict__ v) {
    __shared__ float tile[32][33];
    int m0 = blockIdx.x * 32;
    int c0 = blockIdx.y * 32;
    int tx = threadIdx.x, ty = threadIdx.y;  // 32 x 8
    #pragma unroll
    for (int i = ty; i < 32; i += 8) {
        int m = m0 + tx;
        int c = c0 + i;
        tile[i][tx] = (m < MD) ? v[(size_t)c * MD + m] : 0.f;
    }
    __syncthreads();
    #pragma unroll
    for (int i = ty; i < 32; i += 8) {
        int m = m0 + i;
        int c = c0 + tx;
        if (m < MD) g_vt[(size_t)m * CHD + c] = tile[tx][i];
    }
}

// ---------------- dummy kernel: shifts ncu capture slot onto K1 ---------------
__global__ void k_dummy() { g_dummy_sink[0] = 1.0f; }

// ---------------- K1: fused affinity GEMM (FFMA2) + per-chunk top-20 ----------
// smem float offsets
#define S_AFF   0          // 128q x 132 = 16896 floats; UNION with mk tile (64c x 128m = 8192)
#define S_QK    16896      // 64c x 128q = 8192
#define S_NASQ  25088      // 128
#define S_LV    25216      // 128*20
#define S_LI    27776      // 128*20 (int)
#define S_SCV   30336      // 128*16
#define S_SCI   32384      // 128*16 (int)
#define S_SCNT  34432      // 128 (int)
#define S_TH    34560      // 128
#define S_TOTAL 34688      // floats -> 138752 bytes

__device__ __forceinline__ void list_insert(float* Lv, int* Li, float v, int mg) {
    // strict total order: larger value wins; equal value -> smaller index wins
    if (v > Lv[TOPK - 1] || (v == Lv[TOPK - 1] && mg < Li[TOPK - 1])) {
        int p = TOPK - 1;
        while (p > 0 && (v > Lv[p - 1] || (v == Lv[p - 1] && mg < Li[p - 1]))) {
            Lv[p] = Lv[p - 1]; Li[p] = Li[p - 1]; p--;
        }
        Lv[p] = v; Li[p] = mg;
    }
}

__global__ void __launch_bounds__(512) k_aff_topk(
    const float* __restrict__ qk, const float* __restrict__ mk)
{
    extern __shared__ float smem[];
    float* aff  = smem + S_AFF;   // also mk staging region
    float* qks  = smem + S_QK;
    float* nasq = smem + S_NASQ;
    float* lv   = smem + S_LV;
    int*   li   = (int*)(smem + S_LI);
    float* scv  = smem + S_SCV;
    int*   sci  = (int*)(smem + S_SCI);
    int*   scnt = (int*)(smem + S_SCNT);
    float* th   = smem + S_TH;

    const int tid   = threadIdx.x;
    const int q0    = blockIdx.x * QT;
    const int chunk = blockIdx.y;
    const int mc0   = chunk * CHUNKP;
    const int mlen  = min(CHUNKP, MD - mc0);
    const int iters = (mlen + MT - 1) / MT;

    // init lists / gates / counters
    for (int i = tid; i < QT * TOPK; i += 512) { lv[i] = -3.0e38f; li[i] = 0; }
    if (tid < QT) { scnt[tid] = 0; th[tid] = -3.0e38f; }

    // stage qk tile [64c][128q]
    for (int t = tid; t < CKD * QT; t += 512) {
        int c = t >> 7, j = t & 127;
        int q = q0 + j;
        qks[t] = (q < QD) ? qk[c * QD + q] : 0.f;
    }
    __syncthreads();

    const int tm = tid & 31, tq = tid >> 5;      // GEMM: 32 m-quads x 16 q-octets
    const int qown = tid >> 2, lane4 = tid & 3;  // scan: 128 q x 4 scanners

    for (int it = 0; it < iters; it++) {
        const int m_base = mc0 + it * MT;

        // stage mk tile [64c][128m] via float4 (coalesced) + negated asq
        {
            float4* mk4 = (float4*)aff;
            #pragma unroll 4
            for (int t = tid; t < CKD * (MT / 4); t += 512) {
                int c = t >> 5, f4 = t & 31;
                int mg = m_base + (f4 << 2);
                float4 val = make_float4(0.f, 0.f, 0.f, 0.f);
                if (mg < MD) val = *(const float4*)(mk + (size_t)c * MD + mg);
                mk4[t] = val;   // float off = c*128 + f4*4
            }
            if (tid < MT) {
                int mg = m_base + tid;
                nasq[tid] = (mg < MD) ? g_nasq[mg] : -1.0e37f;
            }
        }
        __syncthreads();

        // packed-f32x2 GEMM: 4 m (2 pairs) x 8 q per thread, c = 0..63
        unsigned long long acc[8][2];
        #pragma unroll
        for (int i = 0; i < 8; i++) { acc[i][0] = 0ull; acc[i][1] = 0ull; }

        const float* mkbase = aff + (tm << 2);
        const float* qbase  = qks + (tq << 3);
        #pragma unroll 4
        for (int c = 0; c < CKD; c++) {
            ulonglong2 a = *(const ulonglong2*)(mkbase + (c << 7));  // m pairs 0,1
            float4 qv0 = *(const float4*)(qbase + (c << 7));
            float4 qv1 = *(const float4*)(qbase + (c << 7) + 4);
            unsigned long long b0 = dup2(qv0.x), b1 = dup2(qv0.y);
            unsigned long long b2 = dup2(qv0.z), b3 = dup2(qv0.w);
            unsigned long long b4 = dup2(qv1.x), b5 = dup2(qv1.y);
            unsigned long long b6 = dup2(qv1.z), b7 = dup2(qv1.w);
            ffma2(acc[0][0], a.x, b0); ffma2(acc[0][1], a.y, b0);
            ffma2(acc[1][0], a.x, b1); ffma2(acc[1][1], a.y, b1);
            ffma2(acc[2][0], a.x, b2); ffma2(acc[2][1], a.y, b2);
            ffma2(acc[3][0], a.x, b3); ffma2(acc[3][1], a.y, b3);
            ffma2(acc[4][0], a.x, b4); ffma2(acc[4][1], a.y, b4);
            ffma2(acc[5][0], a.x, b5); ffma2(acc[5][1], a.y, b5);
            ffma2(acc[6][0], a.x, b6); ffma2(acc[6][1], a.y, b6);
            ffma2(acc[7][0], a.x, b7); ffma2(acc[7][1], a.y, b7);
        }
        __syncthreads();  // all mk reads complete before aff overwrite

        // epilogue: aff = 0.25*dot + (-0.125*asq); rows [q][132]
        {
            ulonglong2 np = *(const ulonglong2*)(nasq + (tm << 2));
            unsigned long long c025 = dup2(0.25f);
            #pragma unroll
            for (int j = 0; j < 8; j++) {
                int qr = (tq << 3) + j;
                ulonglong2 s;
                s.x = ffma2o(acc[j][0], c025, np.x);
                s.y = ffma2o(acc[j][1], c025, np.y);
                *(ulonglong2*)(aff + qr * 132 + (tm << 2)) = s;
            }
        }
        __syncthreads();

        // gated scan: candidates above current 20th-best -> per-q buffer
        {
            float gate = th[qown];
            const float* arow = aff + qown * 132 + lane4;
            #pragma unroll 8
            for (int j = 0; j < 32; j++) {
                float v = arow[j << 2];
                if (v > gate) {
                    int pos = atomicAdd(&scnt[qown], 1);
                    if (pos < CAP) {
                        scv[qown * CAP + pos] = v;
                        sci[qown * CAP + pos] = m_base + lane4 + (j << 2);
                    }
                }
            }
        }
        __syncthreads();

        // merge candidates into per-q sorted top-20 (128 owner threads)
        if (tid < QT) {
            int n = scnt[tid];
            float* Lv = lv + tid * TOPK;
            int*   Li = li + tid * TOPK;
            if (n > CAP) {
                // overflow (first tile of chunk): rescan resident aff row
                const float* arow = aff + tid * 132;
                for (int ml = 0; ml < MT; ml++) {
                    list_insert(Lv, Li, arow[ml], m_base + ml);
                }
            } else {
                for (int i2 = 0; i2 < n; i2++) {
                    list_insert(Lv, Li, scv[tid * CAP + i2], sci[tid * CAP + i2]);
                }
            }
            th[tid] = Lv[TOPK - 1];
            scnt[tid] = 0;
        }
        __syncthreads();
    }

    // writeout per-chunk partial lists, layout [q][chunk][20]
    if (tid < QT) {
        int q = q0 + tid;
        if (q < QD) {
            int ob = (q * NCHUNK + chunk) * TOPK;
            #pragma unroll
            for (int r = 0; r < TOPK; r++) {
                g_pval[ob + r] = lv[tid * TOPK + r];
                g_pidx[ob + r] = li[tid * TOPK + r];
            }
        }
    }
}

// ---------------- K2: warp-per-q rank-count select + softmax ------------------
#define NPOOL (NCHUNK * TOPK)   // 220
__global__ void k_merge_softmax() {
    __shared__ float sv[8][NPOOL];
    __shared__ int   sidx[8][NPOOL];
    int w = threadIdx.x >> 5;
    int lane = threadIdx.x & 31;
    int q = blockIdx.x * 8 + w;
    if (q >= QD) return;

    const float* pv = g_pval + (size_t)q * NPOOL;
    const int*   pi = g_pidx + (size_t)q * NPOOL;
    for (int t = lane; t < NPOOL; t += 32) {
        sv[w][t] = pv[t];
        sidx[w][t] = pi[t];
    }
    __syncwarp();

    // own entries: t = lane + 32*r  (r < 7)
    float ov[7]; int oi[7], orank[7];
    float lmax = -3.4e38f;
    #pragma unroll
    for (int r = 0; r < 7; r++) {
        int t = lane + (r << 5);
        if (t < NPOOL) { ov[r] = sv[w][t]; oi[r] = sidx[w][t]; }
        else           { ov[r] = -3.4e38f; oi[r] = 0x7fffffff; }
        if (ov[r] > lmax) lmax = ov[r];
        orank[r] = 0;
    }
    // global max via warp reduce
    #pragma unroll
    for (int s = 16; s > 0; s >>= 1) {
        float o = __shfl_xor_sync(0xffffffffu, lmax, s);
        if (o > lmax) lmax = o;
    }
    // rank = count of strictly-better entries (val desc, idx asc tiebreak)
    for (int k = 0; k < NPOOL; k++) {
        float vk = sv[w][k];
        int   ik = sidx[w][k];
        #pragma unroll
        for (int r = 0; r < 7; r++) {
            orank[r] += (vk > ov[r] || (vk == ov[r] && ik < oi[r])) ? 1 : 0;
        }
    }
    // softmax over rank < 20
    float lsum = 0.f;
    float oe[7];
    #pragma unroll
    for (int r = 0; r < 7; r++) {
        oe[r] = (orank[r] < TOPK) ? expf(ov[r] - lmax) : 0.f;
        lsum += oe[r];
    }
    #pragma unroll
    for (int s = 16; s > 0; s >>= 1) lsum += __shfl_xor_sync(0xffffffffu, lsum, s);
    float inv = 1.f / lsum;
    #pragma unroll
    for (int r = 0; r < 7; r++) {
        if (orank[r] < TOPK) {
            g_wval[q * TOPK + orank[r]] = oe[r] * inv;
            g_widx[q * TOPK + orank[r]] = oi[r];
        }
    }
}

// ---------------- K3: sparse readout (coalesced gather, packed stores) --------
__global__ void k_readout(float* __restrict__ out) {
    __shared__ float sw[QT3 * TOPK];
    __shared__ int   si[QT3 * TOPK];
    int q0 = blockIdx.x * QT3;
    int ch = blockIdx.y * 256 + threadIdx.x;
    for (int t = threadIdx.x; t < QT3 * TOPK; t += 256) {
        int q = q0 + t / TOPK;
        if (q < QD) {
            sw[t] = g_wval[q * TOPK + (t % TOPK)];
            si[t] = g_widx[q * TOPK + (t % TOPK)];
        } else {
            sw[t] = 0.f;
            si[t] = 0;
        }
    }
    __syncthreads();

    float acc[QT3];
    #pragma unroll
    for (int j = 0; j < QT3; j++) acc[j] = 0.f;

    #pragma unroll
    for (int k = 0; k < TOPK; k++) {
        #pragma unroll
        for (int j = 0; j < QT3; j++) {
            float w = sw[j * TOPK + k];
            int   m = si[j * TOPK + k];
            acc[j] += w * g_vt[(size_t)m * CHD + ch];
        }
    }

    if (q0 + QT3 <= QD) {
        float4* o4 = (float4*)(out + (size_t)ch * QD + q0);
        #pragma unroll
        for (int jj = 0; jj < QT3 / 4; jj++) {
            o4[jj] = make_float4(acc[jj * 4], acc[jj * 4 + 1],
                                 acc[jj * 4 + 2], acc[jj * 4 + 3]);
        }
    } else {
        #pragma unroll
        for (int j = 0; j < QT3; j++) {
            int q = q0 + j;
            if (q < QD) out[(size_t)ch * QD + q] = acc[j];
        }
    }
}

// ---------------- launch ------------------------------------------------------
extern "C" void kernel_launch(void* const* d_in, const int* in_sizes, int n_in,
                              void* d_out, int out_size) {
    const float* qk = (const float*)d_in[0];   // [1,64,30,54] -> [64][1620]
    const float* mk = (const float*)d_in[1];   // [1,64,32400] -> [64][32400]
    const float* mv = (const float*)d_in[2];   // [3,512,32400] -> [1536][32400]
    float* out = (float*)d_out;                // [3,1,512,30,54] -> [1536][1620]
    (void)in_sizes; (void)n_in; (void)out_size;

    k_asq<<<(MD + 255) / 256, 256>>>(mk);

    k_transpose<<<dim3((MD + 31) / 32, CHD / 32), dim3(32, 8)>>>(mv);

    k_dummy<<<1, 1>>>();  // shifts ncu -s5 capture slot onto k_aff_topk

    size_t smem1 = (size_t)S_TOTAL * sizeof(float);  // 138752 bytes
    cudaFuncSetAttribute(k_aff_topk, cudaFuncAttributeMaxDynamicSharedMemorySize, (int)smem1);
    k_aff_topk<<<dim3(NQB, NCHUNK), 512, smem1>>>(qk, mk);

    k_merge_softmax<<<(QD + 7) / 8, 256>>>();

    k_readout<<<dim3((QD + QT3 - 1) / QT3, CHD / 256), 256>>>(out);
}